// round 15
// baseline (speedup 1.0000x reference)
#include <cuda_runtime.h>
#include <cuda_bf16.h>
#include <cuda_fp16.h>
#include <math.h>
#include <cstdint>

// B=4, L=256, Eq=Ek=2, D=512, H=8, dk=dv=64, KG=16
// output float [4,256,2,512]

typedef unsigned long long ull;

__device__ __forceinline__ ull pk(float lo, float hi) {
    ull r; asm("mov.b64 %0,{%1,%2};" : "=l"(r) : "f"(lo), "f"(hi)); return r;
}
__device__ __forceinline__ void fma2(ull& d, ull a, ull b) {
    asm("fma.rn.f32x2 %0,%1,%2,%0;" : "+l"(d) : "l"(a), "l"(b));
}
__device__ __forceinline__ void unpk(float& lo, float& hi, ull a) {
    asm("mov.b64 {%0,%1},%2;" : "=f"(lo), "=f"(hi) : "l"(a));
}
__device__ __forceinline__ uint32_t smem_u32(const void* p) {
    uint32_t a;
    asm("{ .reg .u64 t; cvta.to.shared.u64 t, %1; cvt.u32.u64 %0, t; }" : "=r"(a) : "l"(p));
    return a;
}
__device__ __forceinline__ void ldsm4(uint32_t* r, uint32_t addr) {
    asm volatile("ldmatrix.sync.aligned.m8n8.x4.shared.b16 {%0,%1,%2,%3},[%4];"
        : "=r"(r[0]), "=r"(r[1]), "=r"(r[2]), "=r"(r[3]) : "r"(addr));
}
__device__ __forceinline__ void mma_bf16(float* d, const uint32_t* a, const uint32_t* b) {
    asm volatile(
        "mma.sync.aligned.m16n8k16.row.col.f32.bf16.bf16.f32 "
        "{%0,%1,%2,%3},{%4,%5,%6,%7},{%8,%9},{%0,%1,%2,%3};"
        : "+f"(d[0]), "+f"(d[1]), "+f"(d[2]), "+f"(d[3])
        : "r"(a[0]), "r"(a[1]), "r"(a[2]), "r"(a[3]), "r"(b[0]), "r"(b[1]));
}
__device__ __forceinline__ void mma_f16(float* d, const uint32_t* a, const uint32_t* b) {
    asm volatile(
        "mma.sync.aligned.m16n8k16.row.col.f32.f16.f16.f32 "
        "{%0,%1,%2,%3},{%4,%5,%6,%7},{%8,%9},{%0,%1,%2,%3};"
        : "+f"(d[0]), "+f"(d[1]), "+f"(d[2]), "+f"(d[3])
        : "r"(a[0]), "r"(a[1]), "r"(a[2]), "r"(a[3]), "r"(b[0]), "r"(b[1]));
}

// ---------------- scratch ----------------
__device__ float g_qp [4*256*2*512];
__device__ float g_qp2[4*256*2*512];
__device__ float g_vp [4*256*2*512];
__device__ float g_lsg[4*256*32*256];
__device__ float g_res[4*256*2*512];

__device__ __nv_bfloat16 g_Ahi[3*2*1024*512];   // [tensor][ie][m][k]
__device__ __nv_bfloat16 g_Alo[3*2*1024*512];
__device__ __nv_bfloat16 g_WThi[6*2*512*512];   // [w][ie][n][k]  (w5 = fc)
__device__ __nv_bfloat16 g_WTlo[6*2*512*512];
__device__ __nv_bfloat16 g_Phi[2*1024*512];
__device__ __nv_bfloat16 g_Plo[2*1024*512];

// K for attn scores: [(b*8+h)*2+set][pair 512][d 64] bf16 hi/lo
__device__ __nv_bfloat16 g_Khi[4*8*2*512*64];
__device__ __nv_bfloat16 g_Klo[4*8*2*512*64];

// gate scratch (fp16 single-pass)
__device__ __half g_W1h[32*16*24];
__device__ __half g_Xh[4*256*256*24];

__device__ __forceinline__ void bsplit(float x, __nv_bfloat16& h, __nv_bfloat16& l) {
    h = __float2bfloat16(x);
    l = __float2bfloat16(x - __bfloat162float(h));
}

// ---------------- weight convert + transpose ----------------
__global__ __launch_bounds__(256) void conv_w_kernel(
    const float* __restrict__ Wq, const float* __restrict__ Wq2,
    const float* __restrict__ Wk, const float* __restrict__ Wk2,
    const float* __restrict__ Wv, const float* __restrict__ Wfc)
{
    __shared__ float tile[32][33];
    int z = blockIdx.z;
    int w = z >> 1, ie = z & 1;
    const float* in;
    if (w == 0) in = Wq; else if (w == 1) in = Wq2; else if (w == 2) in = Wk;
    else if (w == 3) in = Wk2; else if (w == 4) in = Wv; else in = Wfc;
    in += (size_t)ie * 262144;

    int k0 = blockIdx.x * 32, n0 = blockIdx.y * 32;
    int tx = threadIdx.x & 31, ty = threadIdx.x >> 5;
#pragma unroll
    for (int j = 0; j < 4; j++) {
        int r = ty + j * 8;
        tile[r][tx] = in[(size_t)(k0 + r) * 512 + n0 + tx];
    }
    __syncthreads();
    size_t ob = ((size_t)(w * 2 + ie) * 512);
#pragma unroll
    for (int j = 0; j < 4; j++) {
        int r = ty + j * 8;
        float v = tile[tx][r];
        __nv_bfloat16 h, l;
        bsplit(v, h, l);
        size_t off = (ob + n0 + r) * 512 + k0 + tx;
        g_WThi[off] = h;
        g_WTlo[off] = l;
    }
}

// ---------------- activation convert (q,k,v) ----------------
__global__ __launch_bounds__(256) void conv_a_kernel(
    const float* __restrict__ q, const float* __restrict__ k, const float* __restrict__ v)
{
    int o4 = blockIdx.x * 256 + threadIdx.x;
    int k4 = o4 & 127;
    int m  = (o4 >> 7) & 1023;
    int ie = (o4 >> 17) & 1;
    int tid = o4 >> 18;
    const float* src = (tid == 0) ? q : (tid == 1) ? k : v;
    float4 val = *(const float4*)(src + ((size_t)(m * 2 + ie) * 512 + k4 * 4));
    __nv_bfloat16 h0, l0, h1, l1, h2, l2, h3, l3;
    bsplit(val.x, h0, l0); bsplit(val.y, h1, l1);
    bsplit(val.z, h2, l2); bsplit(val.w, h3, l3);
    size_t off = ((size_t)(tid * 2 + ie) * 1024 + m) * 512 + k4 * 4;
    *(__nv_bfloat162*)(g_Ahi + off)     = __nv_bfloat162(h0, h1);
    *(__nv_bfloat162*)(g_Ahi + off + 2) = __nv_bfloat162(h2, h3);
    *(__nv_bfloat162*)(g_Alo + off)     = __nv_bfloat162(l0, l1);
    *(__nv_bfloat162*)(g_Alo + off + 2) = __nv_bfloat162(l2, l3);
}

// ---------------- gate X convert (fp16) + W1 convert (last block) ----------------
__global__ __launch_bounds__(256) void conv_x_kernel(
    const float* __restrict__ gr_mask, const float* __restrict__ grW1)
{
    if (blockIdx.x == 1024) {
        for (int i = threadIdx.x; i < 8192; i += 256) {
            int c = i >> 8, g = (i >> 4) & 15, m = i & 15;
            g_W1h[(c * 16 + m) * 24 + g] = __float2half_rn(grW1[i]);
        }
        return;
    }
    int gid = blockIdx.x * 256 + threadIdx.x;
    int b = gid >> 16;
    const float* src = gr_mask + ((size_t)b * 16) * 65536 + (gid & 65535);
    __half hbuf[16];
#pragma unroll
    for (int g = 0; g < 16; g++)
        hbuf[g] = __float2half_rn(src[(size_t)g * 65536]);
    size_t base = (size_t)gid * 24;
    *(uint4*)(g_Xh + base)     = *(const uint4*)hbuf;
    *(uint4*)(g_Xh + base + 8) = *(const uint4*)(hbuf + 8);
}

// ======================================================================
// HMMA GEMM core
// ======================================================================
#define GEMM_SMEM 61440

__device__ __forceinline__ void hmma_mainloop(
    const __nv_bfloat16* __restrict__ gAhi, const __nv_bfloat16* __restrict__ gAlo,
    const __nv_bfloat16* __restrict__ gBhi, const __nv_bfloat16* __restrict__ gBlo,
    float acc[2][4][4])
{
    extern __shared__ __nv_bfloat16 smb[];
    char* smc = (char*)smb;

    int t = threadIdx.x;
    int lane = t & 31, warp = t >> 5;
    int wm = (warp & 3) * 32, wn = (warp >> 2) * 32;

    int a_r = t >> 2, a_q = t & 3;

    uint32_t sb = smem_u32(smb);
    int arow = lane & 15, asel = lane >> 4;
    uint32_t aAddr = sb + (uint32_t)((wm + arow) * 80 + asel * 16);
    int brow = (lane & 7) + ((lane >> 4) & 1) * 8;
    int bsel = (lane >> 3) & 1;
    uint32_t bAddr = sb + 40960u + (uint32_t)((wn + brow) * 80 + bsel * 16);

    uint4 ra_hi0, ra_hi1, ra_lo0, ra_lo1, rb_hi, rb_lo;

#define LOAD_TILE(kt) do { \
    int kk = (kt) * 32 + a_q * 8; \
    ra_hi0 = *(const uint4*)(gAhi + (size_t)a_r * 512 + kk); \
    ra_hi1 = *(const uint4*)(gAhi + (size_t)(a_r + 64) * 512 + kk); \
    ra_lo0 = *(const uint4*)(gAlo + (size_t)a_r * 512 + kk); \
    ra_lo1 = *(const uint4*)(gAlo + (size_t)(a_r + 64) * 512 + kk); \
    rb_hi  = *(const uint4*)(gBhi + (size_t)a_r * 512 + kk); \
    rb_lo  = *(const uint4*)(gBlo + (size_t)a_r * 512 + kk); \
} while (0)

#define STORE_TILE(s) do { \
    int ao = a_r * 80 + a_q * 16; \
    *(uint4*)(smc + (s) * 10240 + ao) = ra_hi0; \
    *(uint4*)(smc + (s) * 10240 + ao + 64 * 80) = ra_hi1; \
    *(uint4*)(smc + 20480 + (s) * 10240 + ao) = ra_lo0; \
    *(uint4*)(smc + 20480 + (s) * 10240 + ao + 64 * 80) = ra_lo1; \
    if (a_r < 64) { \
        *(uint4*)(smc + 40960 + (s) * 5120 + ao) = rb_hi; \
        *(uint4*)(smc + 51200 + (s) * 5120 + ao) = rb_lo; \
    } \
} while (0)

    LOAD_TILE(0);
    STORE_TILE(0);
    __syncthreads();

    for (int kt = 0; kt < 16; kt++) {
        if (kt < 15) LOAD_TILE(kt + 1);
        int s = kt & 1;
        uint32_t as  = aAddr + s * 10240;
        uint32_t als = as + 20480;
        uint32_t bs  = bAddr + s * 5120;
        uint32_t bls = bs + 10240;
#pragma unroll
        for (int ks2 = 0; ks2 < 2; ks2++) {
            uint32_t ka = ks2 * 32;
            uint32_t ahi[2][4], alo[2][4], bhi[2][4], blo[2][4];
            ldsm4(ahi[0], as + ka);
            ldsm4(ahi[1], as + 1280 + ka);
            ldsm4(alo[0], als + ka);
            ldsm4(alo[1], als + 1280 + ka);
            ldsm4(bhi[0], bs + ka);
            ldsm4(bhi[1], bs + 1280 + ka);
            ldsm4(blo[0], bls + ka);
            ldsm4(blo[1], bls + 1280 + ka);
#pragma unroll
            for (int mt = 0; mt < 2; mt++) {
#pragma unroll
                for (int nt = 0; nt < 4; nt++) {
                    const uint32_t* bh = &bhi[nt >> 1][(nt & 1) * 2];
                    const uint32_t* bl = &blo[nt >> 1][(nt & 1) * 2];
                    mma_bf16(acc[mt][nt], ahi[mt], bh);
                    mma_bf16(acc[mt][nt], ahi[mt], bl);
                    mma_bf16(acc[mt][nt], alo[mt], bh);
                }
            }
        }
        if (kt < 15) STORE_TILE((kt + 1) & 1);
        __syncthreads();
    }
#undef LOAD_TILE
#undef STORE_TILE
}

// ---------------- proj HMMA ----------------
__global__ __launch_bounds__(256, 2) void proj_mma_kernel()
{
    int m0 = blockIdx.x * 128;
    int n0 = blockIdx.y * 64;
    int z = blockIdx.z;
    int proj = z >> 1, ie = z & 1;
    int tid = (proj <= 1) ? 0 : (proj <= 3) ? 1 : 2;

    const __nv_bfloat16* ahi = g_Ahi + ((size_t)(tid * 2 + ie) * 1024 + m0) * 512;
    const __nv_bfloat16* alo = g_Alo + ((size_t)(tid * 2 + ie) * 1024 + m0) * 512;
    const __nv_bfloat16* bhi = g_WThi + ((size_t)(proj * 2 + ie) * 512 + n0) * 512;
    const __nv_bfloat16* blo = g_WTlo + ((size_t)(proj * 2 + ie) * 512 + n0) * 512;

    float acc[2][4][4];
#pragma unroll
    for (int a = 0; a < 2; a++)
#pragma unroll
        for (int b = 0; b < 4; b++)
#pragma unroll
            for (int c = 0; c < 4; c++) acc[a][b][c] = 0.f;

    hmma_mainloop(ahi, alo, bhi, blo, acc);

    int t = threadIdx.x, lane = t & 31, warp = t >> 5;
    int wm = (warp & 3) * 32, wn = (warp >> 2) * 32;
    int r_in = lane >> 2, cc = (lane & 3) * 2;

    if (proj == 2 || proj == 3) {
        int set = proj - 2;
#pragma unroll
        for (int mt = 0; mt < 2; mt++) {
#pragma unroll
            for (int nt = 0; nt < 4; nt++) {
                int f0 = n0 + wn + nt * 8 + cc;   // even, dd/dd+1 same h
                int hh = f0 >> 6, dd = f0 & 63;
#pragma unroll
                for (int half = 0; half < 2; half++) {
                    int m = m0 + wm + mt * 16 + r_in + half * 8;
                    int bb = m >> 8, ll = m & 255;
                    int pair = ll * 2 + ie;
                    __nv_bfloat16 h0, l0, h1, l1;
                    bsplit(acc[mt][nt][half * 2 + 0], h0, l0);
                    bsplit(acc[mt][nt][half * 2 + 1], h1, l1);
                    size_t off = (((size_t)((bb * 8 + hh) * 2 + set) * 512 + pair) * 64 + dd);
                    *(__nv_bfloat162*)(g_Khi + off) = __nv_bfloat162(h0, h1);
                    *(__nv_bfloat162*)(g_Klo + off) = __nv_bfloat162(l0, l1);
                }
            }
        }
    } else {
        float* dst = (proj == 0) ? g_qp : (proj == 1) ? g_qp2 : g_vp;
#pragma unroll
        for (int mt = 0; mt < 2; mt++) {
#pragma unroll
            for (int nt = 0; nt < 4; nt++) {
                int f0 = n0 + wn + nt * 8 + cc;
#pragma unroll
                for (int half = 0; half < 2; half++) {
                    int m = m0 + wm + mt * 16 + r_in + half * 8;
                    float2 st = make_float2(acc[mt][nt][half * 2], acc[mt][nt][half * 2 + 1]);
                    *(float2*)(dst + ((size_t)m * 2 + ie) * 512 + f0) = st;
                }
            }
        }
    }
}

// ---------------- fc HMMA (+residual) ----------------
__global__ __launch_bounds__(256, 2) void fc_mma_kernel(const float* __restrict__ qin)
{
    int m0 = blockIdx.x * 128;
    int n0 = blockIdx.y * 64;
    int ie = blockIdx.z;

    const __nv_bfloat16* ahi = g_Phi + ((size_t)ie * 1024 + m0) * 512;
    const __nv_bfloat16* alo = g_Plo + ((size_t)ie * 1024 + m0) * 512;
    const __nv_bfloat16* bhi = g_WThi + ((size_t)(10 + ie) * 512 + n0) * 512;
    const __nv_bfloat16* blo = g_WTlo + ((size_t)(10 + ie) * 512 + n0) * 512;

    float acc[2][4][4];
#pragma unroll
    for (int a = 0; a < 2; a++)
#pragma unroll
        for (int b = 0; b < 4; b++)
#pragma unroll
            for (int c = 0; c < 4; c++) acc[a][b][c] = 0.f;

    hmma_mainloop(ahi, alo, bhi, blo, acc);

    int t = threadIdx.x, lane = t & 31, warp = t >> 5;
    int wm = (warp & 3) * 32, wn = (warp >> 2) * 32;
    int r_in = lane >> 2, cc = (lane & 3) * 2;

#pragma unroll
    for (int mt = 0; mt < 2; mt++) {
#pragma unroll
        for (int nt = 0; nt < 4; nt++) {
            int f0 = n0 + wn + nt * 8 + cc;
#pragma unroll
            for (int half = 0; half < 2; half++) {
                int m = m0 + wm + mt * 16 + r_in + half * 8;
                size_t off = ((size_t)m * 2 + ie) * 512 + f0;
                float2 rv = *(const float2*)(qin + off);
                float2 st = make_float2(acc[mt][nt][half * 2] + rv.x,
                                        acc[mt][nt][half * 2 + 1] + rv.y);
                *(float2*)(g_res + off) = st;
            }
        }
    }
}

// ======================================================================
// gate MLP via fp16 HMMA (single pass), 4 q per block
// ======================================================================
#define GOFF_XH   24576
#define GOFF_BW   73728
#define GOFF_B2   77824
#define GATE_SMEM 77952

__device__ __forceinline__ float lsgf(float a) {
    return fminf(a, 0.f) - __logf(1.f + __expf(-fabsf(a)));
}

__global__ __launch_bounds__(256, 2) void gate_mma_kernel(
    const float* __restrict__ grb1, const float* __restrict__ grW2,
    const float* __restrict__ grb2)
{
    extern __shared__ char gsm[];
    uint4* smW1 = (uint4*)gsm;
    uint4* smX  = (uint4*)(gsm + GOFF_XH);
    float2* bw = (float2*)(gsm + GOFF_BW);
    float* b2s = (float*)(gsm + GOFF_B2);

    int t = threadIdx.x, lane = t & 31, w = t >> 5;
    int blk = blockIdx.x, b = blk >> 6, q0 = (blk & 63) * 4;

    const uint4* srcW1 = (const uint4*)g_W1h;
    size_t xb = ((size_t)(b * 256 + q0)) * 6144;
    const uint4* srcX = (const uint4*)(g_Xh + xb);
#pragma unroll
    for (int i = 0; i < 6; i++) {
        int idx = t + i * 256;
        smW1[idx] = srcW1[idx];
    }
#pragma unroll
    for (int i = 0; i < 12; i++) {
        int idx = t + i * 256;
        smX[idx] = srcX[idx];
    }
    for (int idx = t; idx < 512; idx += 256) {
        int c = idx >> 4, jj = (idx >> 2) & 3, s = idx & 3;
        int m = (s >> 1) * 8 + 2 * jj + (s & 1);
        bw[idx] = make_float2(grb1[c * 16 + m], grW2[c * 16 + m]);
    }
    if (t < 32) b2s[t] = grb2[t];
    __syncthreads();

    uint32_t sb = smem_u32(gsm);
    int r0 = w * 32;

    uint32_t ah[4][2][4];
#pragma unroll
    for (int qq = 0; qq < 4; qq++) {
        uint32_t a0 = sb + GOFF_XH +
            (uint32_t)((qq * 256 + r0 + (lane & 15)) * 48 + (lane >> 4) * 16);
        ldsm4(ah[qq][0], a0);
        ldsm4(ah[qq][1], a0 + 16 * 48);
    }

    int j = lane & 3, rg = lane >> 2;
    uint32_t bAddrBase = sb +
        (uint32_t)((((lane & 7) + ((lane >> 4) & 1) * 8)) * 48 + ((lane >> 3) & 1) * 16);
    float* outb = g_lsg + ((size_t)(b * 256 + q0)) * 8192;

    for (int c = 0; c < 32; c++) {
        uint32_t bh[4];
        ldsm4(bh, bAddrBase + (uint32_t)(c * 768));

        float acc[4][2][2][4];
#pragma unroll
        for (int qq = 0; qq < 4; qq++)
#pragma unroll
            for (int rt = 0; rt < 2; rt++)
#pragma unroll
                for (int nt = 0; nt < 2; nt++)
#pragma unroll
                    for (int e = 0; e < 4; e++) acc[qq][rt][nt][e] = 0.f;

#pragma unroll
        for (int qq = 0; qq < 4; qq++)
#pragma unroll
            for (int rt = 0; rt < 2; rt++)
#pragma unroll
                for (int nt = 0; nt < 2; nt++)
                    mma_f16(acc[qq][rt][nt], ah[qq][rt], &bh[nt * 2]);

        float2 p[4];
        *(float4*)&p[0] = *(const float4*)&bw[(c * 4 + j) * 4];
        *(float4*)&p[2] = *(const float4*)&bw[(c * 4 + j) * 4 + 2];
        float b2 = b2s[c];

#pragma unroll
        for (int qq = 0; qq < 4; qq++) {
            float v[4];
#pragma unroll
            for (int rt = 0; rt < 2; rt++) {
                float s0 = 0.f, s1 = 0.f;
#pragma unroll
                for (int nt = 0; nt < 2; nt++) {
#pragma unroll
                    for (int e = 0; e < 2; e++) {
                        int s = nt * 2 + e;
                        s0 += fmaxf(acc[qq][rt][nt][e]     + p[s].x, 0.f) * p[s].y;
                        s1 += fmaxf(acc[qq][rt][nt][2 + e] + p[s].x, 0.f) * p[s].y;
                    }
                }
                v[rt * 2] = s0; v[rt * 2 + 1] = s1;
            }
#pragma unroll
            for (int o = 1; o <= 2; o <<= 1) {
#pragma unroll
                for (int i = 0; i < 4; i++) v[i] += __shfl_xor_sync(0xffffffffu, v[i], o);
            }
            if (j == 0) {
                float* ob = outb + (size_t)qq * 8192;
                int lbase = r0 + rg;
                ob[c * 256 + lbase]      = lsgf(v[0] + b2);
                ob[c * 256 + lbase + 8]  = lsgf(v[1] + b2);
                ob[c * 256 + lbase + 16] = lsgf(v[2] + b2);
                ob[c * 256 + lbase + 24] = lsgf(v[3] + b2);
            }
        }
    }
}

// ======================================================================
// fused attention — HMMA scores + scalar softmax/PV
// Smem (bytes):
//   Q  [2 set][2 half][16][72] bf16   offset 0      (9216)
//   K  [2 set][2 half][64][72] bf16   offset 9216   (36864)  (expb aliases)
//   ss2 [16][256] float2              offset 46080  (32768)  (spv aliases)
//   ssum [16] float                   offset 78848
// ======================================================================
#define AOFF_K    9216
#define AOFF_SS   46080
#define AOFF_EXP  9216
#define AOFF_SSUM 78848
#define ATTN_SMEM 78912

__global__ __launch_bounds__(256, 2) void attn_kernel(
    const float* __restrict__ adj, const int* __restrict__ mask)
{
    extern __shared__ char dsm[];
    float2* ss2  = (float2*)(dsm + AOFF_SS);
    float2* expb = (float2*)(dsm + AOFF_EXP);
    float*  ssum = (float*)(dsm + AOFF_SSUM);

    int bx = blockIdx.x;
    int qt = bx & 15;
    int h  = (bx >> 4) & 7;
    int ie = (bx >> 7) & 1;
    int b  = bx >> 8;
    int q0 = qt * 16;
    int bh = b * 8 + h;

    int t = threadIdx.x;
    int lane = t & 31, w = t >> 5;
    uint32_t sb = smem_u32(dsm);

    // -------- Q prologue: bsplit into smem --------
#pragma unroll
    for (int i = 0; i < 4; i++) {
        int idx = t + i * 256;
        int qq = idx >> 6, d = idx & 63;
        size_t off = ((size_t)(b * 256 + q0 + qq) * 2 + ie) * 512 + h * 64 + d;
        __nv_bfloat16 h0, l0;
        bsplit(g_qp[off], h0, l0);
        *(__nv_bfloat16*)(dsm + 0    + qq * 144 + d * 2) = h0;   // set0 hi
        *(__nv_bfloat16*)(dsm + 2304 + qq * 144 + d * 2) = l0;   // set0 lo
        bsplit(g_qp2[off], h0, l0);
        *(__nv_bfloat16*)(dsm + 4608 + qq * 144 + d * 2) = h0;   // set1 hi
        *(__nv_bfloat16*)(dsm + 6912 + qq * 144 + d * 2) = l0;   // set1 lo
    }

    // -------- score phase: 8 chunks of 64 pairs --------
    int c0i = (ie * 2 + 0) * 8 + h;
    int c1i = (ie * 2 + 1) * 8 + h;
    uint32_t aBase = sb + (uint32_t)((lane & 15) * 144 + (lane >> 4) * 16);
    uint32_t bBase = sb + AOFF_K + (uint32_t)((w * 8 + (lane & 7)) * 144 + (lane >> 3) * 16);

    for (int ch = 0; ch < 8; ch++) {
        // load K chunk: 4 tensors (set,half) x 64 rows x 128B
        __syncthreads();   // previous chunk's ldsm done before overwrite
#pragma unroll
        for (int i = 0; i < 8; i++) {
            int u = t + i * 256;
            int set = (u >> 10) & 1, half = (u >> 9) & 1;
            int r = (u >> 3) & 63, seg = u & 7;
            const __nv_bfloat16* gk = half ? g_Klo : g_Khi;
            uint4 val = *(const uint4*)(gk + (((size_t)(bh * 2 + set) * 512 + ch * 64 + r) * 64 + seg * 8));
            *(uint4*)(dsm + AOFF_K + (set * 2 + half) * 9216 + r * 144 + seg * 16) = val;
        }
        __syncthreads();

        float acc0[4] = {0.f, 0.f, 0.f, 0.f};
        float acc1[4] = {0.f, 0.f, 0.f, 0.f};
#pragma unroll
        for (int kh = 0; kh < 2; kh++) {
            uint32_t ka = kh * 64;
            uint32_t a0h[2][4], a0l[2][4], a1h[2][4], a1l[2][4];
#pragma unroll
            for (int ks = 0; ks < 2; ks++) {
                uint32_t ko = ka + ks * 32;
                ldsm4(a0h[ks], aBase + ko);
                ldsm4(a0l[ks], aBase + 2304 + ko);
                ldsm4(a1h[ks], aBase + 4608 + ko);
                ldsm4(a1l[ks], aBase + 6912 + ko);
            }
            uint32_t b0h[4], b0l[4], b1h[4], b1l[4];
            ldsm4(b0h, bBase + ka);
            ldsm4(b0l, bBase + 9216 + ka);
            ldsm4(b1h, bBase + 18432 + ka);
            ldsm4(b1l, bBase + 27648 + ka);
#pragma unroll
            for (int ks = 0; ks < 2; ks++) {
                mma_bf16(acc0, a0h[ks], &b0h[ks * 2]);
                mma_bf16(acc0, a0h[ks], &b0l[ks * 2]);
                mma_bf16(acc0, a0l[ks], &b0h[ks * 2]);
                mma_bf16(acc1, a1h[ks], &b1h[ks * 2]);
                mma_bf16(acc1, a1h[ks], &b1l[ks * 2]);
                mma_bf16(acc1, a1l[ks], &b1h[ks * 2]);
            }
        }

        // epilogue: blend + gate + mask, write ss2[q][kk]
        int kk = ch * 32 + w * 4 + (lane & 3);
#pragma unroll
        for (int half = 0; half < 2; half++) {
            int qq = (lane >> 2) + half * 8;
            int qi = q0 + qq;
            int mrow = b * 65536 + qi * 256 + kk;
            int mv = mask[mrow];
            float sa, sbv;
            if (mv == 0) {
                sa = -1e9f; sbv = -1e9f;
            } else {
                float at = (kk <= qi) ? adj[mrow] : 0.f;
                size_t lbase = ((size_t)(b * 256 + qi) * 32) * 256 + kk;
                float l0 = g_lsg[lbase + (size_t)c0i * 256];
                float l1 = g_lsg[lbase + (size_t)c1i * 256];
                sa  = (acc0[half * 2 + 0] * at + acc1[half * 2 + 0] * (1.f - at)) * 0.125f + l0;
                sbv = (acc0[half * 2 + 1] * at + acc1[half * 2 + 1] * (1.f - at)) * 0.125f + l1;
            }
            ss2[qq * 256 + kk] = make_float2(sa, sbv);
        }
    }
    __syncthreads();

    // -------- softmax: warp w handles rows 2w, 2w+1; writes expb[p][col] --------
    {
        float2* r0 = ss2 + (2 * w) * 256;
        float2* r1 = r0 + 256;
        float2 v0[8], v1[8];
        float mx0 = -1e30f, mx1 = -1e30f;
#pragma unroll
        for (int i = 0; i < 8; i++) {
            v0[i] = r0[lane + 32 * i];
            v1[i] = r1[lane + 32 * i];
            mx0 = fmaxf(mx0, fmaxf(v0[i].x, v0[i].y));
            mx1 = fmaxf(mx1, fmaxf(v1[i].x, v1[i].y));
        }
#pragma unroll
        for (int o = 16; o > 0; o >>= 1) {
            mx0 = fmaxf(mx0, __shfl_xor_sync(0xffffffffu, mx0, o));
            mx1 = fmaxf(mx1, __shfl_xor_sync(0xffffffffu, mx1, o));
        }
        float s0 = 0.f, s1 = 0.f;
#pragma unroll
        for (int i = 0; i < 8; i++) {
            v0[i].x = __expf(v0[i].x - mx0); v0[i].y = __expf(v0[i].y - mx0);
            v1[i].x = __expf(v1[i].x - mx1); v1[i].y = __expf(v1[i].y - mx1);
            s0 += v0[i].x + v0[i].y;
            s1 += v1[i].x + v1[i].y;
        }
#pragma unroll
        for (int o = 16; o > 0; o >>= 1) {
            s0 += __shfl_xor_sync(0xffffffffu, s0, o);
            s1 += __shfl_xor_sync(0xffffffffu, s1, o);
        }
        if (lane == 0) { ssum[2 * w] = s0; ssum[2 * w + 1] = s1; }
        __syncwarp();
#pragma unroll
        for (int i = 0; i < 8; i++) {
            int c = lane + 32 * i;
            int pa = 2 * c, pb = 2 * c + 1;
            expb[pa * 8 + ((w + pa + (pa >> 3)) & 7)] = make_float2(v0[i].x, v1[i].x);
            expb[pb * 8 + ((w + pb + (pb >> 3)) & 7)] = make_float2(v0[i].y, v1[i].y);
        }
    }
    __syncthreads();

    // -------- PV phase --------
    {
        int d = t & 63, grp = t >> 6;
        const float* vb = g_vp + ((size_t)b * 512) * 512 + h * 64 + d;
        ull o[8];
#pragma unroll
        for (int r = 0; r < 8; r++) o[r] = 0ull;
        int p0 = grp * 128;
#pragma unroll 64
        for (int pp = 0; pp < 128; pp++) {
            int p = p0 + pp;
            const ulonglong2* row = (const ulonglong2*)(expb + (size_t)p * 8);
            ulonglong2 e0 = row[0], e1 = row[1], e2 = row[2], e3 = row[3];
            ull ev[8] = {e0.x, e0.y, e1.x, e1.y, e2.x, e2.y, e3.x, e3.y};
            float v = __ldg(vb + (size_t)p * 512);
            ull vd = pk(v, v);
            int rot = (pp + (pp >> 3)) & 7;
#pragma unroll
            for (int r = 0; r < 8; r++) fma2(o[r], ev[(r + rot) & 7], vd);
        }
        __syncthreads();
        float* spv = (float*)(dsm + AOFF_SS);
        if (grp) {
            float* sp = spv + (grp - 1) * 1024;
#pragma unroll
            for (int r = 0; r < 8; r++) {
                float lo, hi;
                unpk(lo, hi, o[r]);
                sp[(2 * r) * 64 + d] = lo;
                sp[(2 * r + 1) * 64 + d] = hi;
            }
        }
        __syncthreads();
        if (grp == 0) {
#pragma unroll
            for (int r = 0; r < 8; r++) {
                float lo, hi;
                unpk(lo, hi, o[r]);
                float sum0 = lo + spv[(2 * r) * 64 + d] + spv[1024 + (2 * r) * 64 + d] + spv[2048 + (2 * r) * 64 + d];
                float sum1 = hi + spv[(2 * r + 1) * 64 + d] + spv[1024 + (2 * r + 1) * 64 + d] + spv[2048 + (2 * r + 1) * 64 + d];
                int qq0 = 2 * r, qq1 = 2 * r + 1;
                float o0 = sum0 / ssum[qq0];
                float o1 = sum1 / ssum[qq1];
                __nv_bfloat16 ph0, pl0, ph1, pl1;
                bsplit(o0, ph0, pl0);
                bsplit(o1, ph1, pl1);
                size_t row0 = (size_t)ie * 1024 + (b * 256 + q0 + qq0);
                size_t off0 = row0 * 512 + h * 64 + d;
                size_t off1 = off0 + 512;
                g_Phi[off0] = ph0; g_Plo[off0] = pl0;
                g_Phi[off1] = ph1; g_Plo[off1] = pl1;
            }
        }
    }
}

// ---------------- layernorm ----------------
__global__ __launch_bounds__(128) void ln_kernel(
    const float* __restrict__ ln_g, const float* __restrict__ ln_b,
    float* __restrict__ out)
{
    __shared__ float rs[4], rq[4];
    __shared__ float s_mu, s_inv;
    int row = blockIdx.x;
    int t = threadIdx.x;
    const float4 v = ((const float4*)(g_res + (size_t)row * 512))[t];
    float sum = v.x + v.y + v.z + v.w;
    float sq  = v.x * v.x + v.y * v.y + v.z * v.z + v.w * v.w;
#pragma unroll
    for (int o = 16; o > 0; o >>= 1) {
        sum += __shfl_xor_sync(0xffffffffu, sum, o);
        sq  += __shfl_xor_sync(0xffffffffu, sq, o);
    }
    int lane = t & 31, warp = t >> 5;
    if (lane == 0) { rs[warp] = sum; rq[warp] = sq; }
    __syncthreads();
    if (t == 0) {
        float S = rs[0] + rs[1] + rs[2] + rs[3];
        float Q = rq[0] + rq[1] + rq[2] + rq[3];
        float mu = S * (1.f / 512.f);
        float var = Q * (1.f / 512.f) - mu * mu;
        s_mu = mu;
        s_inv = rsqrtf(var + 1e-6f);
    }
    __syncthreads();
    float mu = s_mu, inv = s_inv;
    float4 g4 = ((const float4*)ln_g)[t];
    float4 b4 = ((const float4*)ln_b)[t];
    float4 y;
    y.x = (v.x - mu) * inv * g4.x + b4.x;
    y.y = (v.y - mu) * inv * g4.y + b4.y;
    y.z = (v.z - mu) * inv * g4.z + b4.z;
    y.w = (v.w - mu) * inv * g4.w + b4.w;
    ((float4*)(out + (size_t)row * 512))[t] = y;
}

extern "C" void kernel_launch(void* const* d_in, const int* in_sizes, int n_in,
                              void* d_out, int out_size) {
    const float* q       = (const float*)d_in[0];
    const float* k       = (const float*)d_in[1];
    const float* v       = (const float*)d_in[2];
    const int*   mask    = (const int*)d_in[3];
    const float* gr_mask = (const float*)d_in[4];
    const float* adj     = (const float*)d_in[5];
    const float* Wq      = (const float*)d_in[6];
    const float* Wk      = (const float*)d_in[7];
    const float* Wv      = (const float*)d_in[8];
    const float* Wq2     = (const float*)d_in[9];
    const float* Wk2     = (const float*)d_in[10];
    const float* Wfc     = (const float*)d_in[12];
    const float* grW1    = (const float*)d_in[13];
    const float* grb1    = (const float*)d_in[14];
    const float* grW2    = (const float*)d_in[15];
    const float* grb2    = (const float*)d_in[16];
    const float* ln_g    = (const float*)d_in[17];
    const float* ln_b    = (const float*)d_in[18];
    float* out = (float*)d_out;

    cudaFuncSetAttribute(proj_mma_kernel, cudaFuncAttributeMaxDynamicSharedMemorySize, GEMM_SMEM);
    cudaFuncSetAttribute(fc_mma_kernel, cudaFuncAttributeMaxDynamicSharedMemorySize, GEMM_SMEM);
    cudaFuncSetAttribute(gate_mma_kernel, cudaFuncAttributeMaxDynamicSharedMemorySize, GATE_SMEM);
    cudaFuncSetAttribute(attn_kernel, cudaFuncAttributeMaxDynamicSharedMemorySize, ATTN_SMEM);

    static cudaStream_t s1 = nullptr, s2 = nullptr, s3 = nullptr;
    static cudaEvent_t e0 = nullptr, e1 = nullptr, e2 = nullptr, e3 = nullptr;
    if (s1 == nullptr) {
        cudaStreamCreateWithFlags(&s1, cudaStreamNonBlocking);
        cudaStreamCreateWithFlags(&s2, cudaStreamNonBlocking);
        cudaStreamCreateWithFlags(&s3, cudaStreamNonBlocking);
        cudaEventCreateWithFlags(&e0, cudaEventDisableTiming);
        cudaEventCreateWithFlags(&e1, cudaEventDisableTiming);
        cudaEventCreateWithFlags(&e2, cudaEventDisableTiming);
        cudaEventCreateWithFlags(&e3, cudaEventDisableTiming);
    }

    cudaEventRecord(e0, 0);
    cudaStreamWaitEvent(s1, e0, 0);
    cudaStreamWaitEvent(s2, e0, 0);
    cudaStreamWaitEvent(s3, e0, 0);

    // chain A: weights on s1, activations on s3, proj joins both on s1
    conv_w_kernel<<<dim3(16, 16, 12), 256, 0, s1>>>(Wq, Wq2, Wk, Wk2, Wv, Wfc);
    conv_a_kernel<<<3072, 256, 0, s3>>>(q, k, v);
    cudaEventRecord(e3, s3);
    cudaStreamWaitEvent(s1, e3, 0);
    proj_mma_kernel<<<dim3(8, 8, 10), 256, GEMM_SMEM, s1>>>();
    cudaEventRecord(e1, s1);

    // chain B: gate (fp16 single-pass)
    conv_x_kernel<<<1025, 256, 0, s2>>>(gr_mask, grW1);
    gate_mma_kernel<<<256, 256, GATE_SMEM, s2>>>(grb1, grW2, grb2);
    cudaEventRecord(e2, s2);

    // join
    cudaStreamWaitEvent(0, e1, 0);
    cudaStreamWaitEvent(0, e2, 0);

    attn_kernel<<<1024, 256, ATTN_SMEM>>>(adj, mask);
    fc_mma_kernel<<<dim3(8, 8, 2), 256, GEMM_SMEM>>>(q);
    ln_kernel<<<2048, 128>>>(ln_g, ln_b, out);
}

// round 16
// speedup vs baseline: 1.1014x; 1.1014x over previous
#include <cuda_runtime.h>
#include <cuda_bf16.h>
#include <cuda_fp16.h>
#include <math.h>
#include <cstdint>

// B=4, L=256, Eq=Ek=2, D=512, H=8, dk=dv=64, KG=16
// output float [4,256,2,512]

typedef unsigned long long ull;

__device__ __forceinline__ ull pk(float lo, float hi) {
    ull r; asm("mov.b64 %0,{%1,%2};" : "=l"(r) : "f"(lo), "f"(hi)); return r;
}
__device__ __forceinline__ void fma2(ull& d, ull a, ull b) {
    asm("fma.rn.f32x2 %0,%1,%2,%0;" : "+l"(d) : "l"(a), "l"(b));
}
__device__ __forceinline__ void unpk(float& lo, float& hi, ull a) {
    asm("mov.b64 {%0,%1},%2;" : "=f"(lo), "=f"(hi) : "l"(a));
}
__device__ __forceinline__ uint32_t smem_u32(const void* p) {
    uint32_t a;
    asm("{ .reg .u64 t; cvta.to.shared.u64 t, %1; cvt.u32.u64 %0, t; }" : "=r"(a) : "l"(p));
    return a;
}
__device__ __forceinline__ void ldsm4(uint32_t* r, uint32_t addr) {
    asm volatile("ldmatrix.sync.aligned.m8n8.x4.shared.b16 {%0,%1,%2,%3},[%4];"
        : "=r"(r[0]), "=r"(r[1]), "=r"(r[2]), "=r"(r[3]) : "r"(addr));
}
__device__ __forceinline__ void mma_bf16(float* d, const uint32_t* a, const uint32_t* b) {
    asm volatile(
        "mma.sync.aligned.m16n8k16.row.col.f32.bf16.bf16.f32 "
        "{%0,%1,%2,%3},{%4,%5,%6,%7},{%8,%9},{%0,%1,%2,%3};"
        : "+f"(d[0]), "+f"(d[1]), "+f"(d[2]), "+f"(d[3])
        : "r"(a[0]), "r"(a[1]), "r"(a[2]), "r"(a[3]), "r"(b[0]), "r"(b[1]));
}
__device__ __forceinline__ void mma_f16(float* d, const uint32_t* a, const uint32_t* b) {
    asm volatile(
        "mma.sync.aligned.m16n8k16.row.col.f32.f16.f16.f32 "
        "{%0,%1,%2,%3},{%4,%5,%6,%7},{%8,%9},{%0,%1,%2,%3};"
        : "+f"(d[0]), "+f"(d[1]), "+f"(d[2]), "+f"(d[3])
        : "r"(a[0]), "r"(a[1]), "r"(a[2]), "r"(a[3]), "r"(b[0]), "r"(b[1]));
}

// ---------------- scratch ----------------
__device__ float g_qp [4*256*2*512];
__device__ float g_qp2[4*256*2*512];
__device__ float g_kpT[4*8*64*512*2];  // [b][h][d][pair][set]
__device__ float g_vp [4*256*2*512];
__device__ float g_lsg[4*256*32*256];
__device__ float g_res[4*256*2*512];

__device__ __nv_bfloat16 g_Ahi[3*2*1024*512];   // [tensor][ie][m][k]
__device__ __nv_bfloat16 g_Alo[3*2*1024*512];
__device__ __nv_bfloat16 g_WThi[6*2*512*512];   // [w][ie][n][k]  (w5 = fc)
__device__ __nv_bfloat16 g_WTlo[6*2*512*512];
__device__ __nv_bfloat16 g_Phi[2*1024*512];
__device__ __nv_bfloat16 g_Plo[2*1024*512];

// gate scratch (fp16 single-pass)
__device__ __half g_W1h[32*16*24];
__device__ __half g_Xh[4*256*256*24];

__device__ __forceinline__ void bsplit(float x, __nv_bfloat16& h, __nv_bfloat16& l) {
    h = __float2bfloat16(x);
    l = __float2bfloat16(x - __bfloat162float(h));
}

// ---------------- weight convert + transpose ----------------
__global__ __launch_bounds__(256) void conv_w_kernel(
    const float* __restrict__ Wq, const float* __restrict__ Wq2,
    const float* __restrict__ Wk, const float* __restrict__ Wk2,
    const float* __restrict__ Wv, const float* __restrict__ Wfc)
{
    __shared__ float tile[32][33];
    int z = blockIdx.z;
    int w = z >> 1, ie = z & 1;
    const float* in;
    if (w == 0) in = Wq; else if (w == 1) in = Wq2; else if (w == 2) in = Wk;
    else if (w == 3) in = Wk2; else if (w == 4) in = Wv; else in = Wfc;
    in += (size_t)ie * 262144;

    int k0 = blockIdx.x * 32, n0 = blockIdx.y * 32;
    int tx = threadIdx.x & 31, ty = threadIdx.x >> 5;
#pragma unroll
    for (int j = 0; j < 4; j++) {
        int r = ty + j * 8;
        tile[r][tx] = in[(size_t)(k0 + r) * 512 + n0 + tx];
    }
    __syncthreads();
    size_t ob = ((size_t)(w * 2 + ie) * 512);
#pragma unroll
    for (int j = 0; j < 4; j++) {
        int r = ty + j * 8;
        float v = tile[tx][r];
        __nv_bfloat16 h, l;
        bsplit(v, h, l);
        size_t off = (ob + n0 + r) * 512 + k0 + tx;
        g_WThi[off] = h;
        g_WTlo[off] = l;
    }
}

// ---------------- activation convert (q,k,v) ----------------
__global__ __launch_bounds__(256) void conv_a_kernel(
    const float* __restrict__ q, const float* __restrict__ k, const float* __restrict__ v)
{
    int o4 = blockIdx.x * 256 + threadIdx.x;
    int k4 = o4 & 127;
    int m  = (o4 >> 7) & 1023;
    int ie = (o4 >> 17) & 1;
    int tid = o4 >> 18;
    const float* src = (tid == 0) ? q : (tid == 1) ? k : v;
    float4 val = *(const float4*)(src + ((size_t)(m * 2 + ie) * 512 + k4 * 4));
    __nv_bfloat16 h0, l0, h1, l1, h2, l2, h3, l3;
    bsplit(val.x, h0, l0); bsplit(val.y, h1, l1);
    bsplit(val.z, h2, l2); bsplit(val.w, h3, l3);
    size_t off = ((size_t)(tid * 2 + ie) * 1024 + m) * 512 + k4 * 4;
    *(__nv_bfloat162*)(g_Ahi + off)     = __nv_bfloat162(h0, h1);
    *(__nv_bfloat162*)(g_Ahi + off + 2) = __nv_bfloat162(h2, h3);
    *(__nv_bfloat162*)(g_Alo + off)     = __nv_bfloat162(l0, l1);
    *(__nv_bfloat162*)(g_Alo + off + 2) = __nv_bfloat162(l2, l3);
}

// ---------------- gate X convert (fp16) + W1 convert (last block) ----------------
__global__ __launch_bounds__(256) void conv_x_kernel(
    const float* __restrict__ gr_mask, const float* __restrict__ grW1)
{
    if (blockIdx.x == 1024) {
        for (int i = threadIdx.x; i < 8192; i += 256) {
            int c = i >> 8, g = (i >> 4) & 15, m = i & 15;
            g_W1h[(c * 16 + m) * 24 + g] = __float2half_rn(grW1[i]);
        }
        return;
    }
    int gid = blockIdx.x * 256 + threadIdx.x;
    int b = gid >> 16;
    const float* src = gr_mask + ((size_t)b * 16) * 65536 + (gid & 65535);
    __half hbuf[16];
#pragma unroll
    for (int g = 0; g < 16; g++)
        hbuf[g] = __float2half_rn(src[(size_t)g * 65536]);
    size_t base = (size_t)gid * 24;
    *(uint4*)(g_Xh + base)     = *(const uint4*)hbuf;
    *(uint4*)(g_Xh + base + 8) = *(const uint4*)(hbuf + 8);
}

// ======================================================================
// HMMA GEMM core
// ======================================================================
#define GEMM_SMEM 61440

__device__ __forceinline__ void hmma_mainloop(
    const __nv_bfloat16* __restrict__ gAhi, const __nv_bfloat16* __restrict__ gAlo,
    const __nv_bfloat16* __restrict__ gBhi, const __nv_bfloat16* __restrict__ gBlo,
    float acc[2][4][4])
{
    extern __shared__ __nv_bfloat16 smb[];
    char* smc = (char*)smb;

    int t = threadIdx.x;
    int lane = t & 31, warp = t >> 5;
    int wm = (warp & 3) * 32, wn = (warp >> 2) * 32;

    int a_r = t >> 2, a_q = t & 3;

    uint32_t sb = smem_u32(smb);
    int arow = lane & 15, asel = lane >> 4;
    uint32_t aAddr = sb + (uint32_t)((wm + arow) * 80 + asel * 16);
    int brow = (lane & 7) + ((lane >> 4) & 1) * 8;
    int bsel = (lane >> 3) & 1;
    uint32_t bAddr = sb + 40960u + (uint32_t)((wn + brow) * 80 + bsel * 16);

    uint4 ra_hi0, ra_hi1, ra_lo0, ra_lo1, rb_hi, rb_lo;

#define LOAD_TILE(kt) do { \
    int kk = (kt) * 32 + a_q * 8; \
    ra_hi0 = *(const uint4*)(gAhi + (size_t)a_r * 512 + kk); \
    ra_hi1 = *(const uint4*)(gAhi + (size_t)(a_r + 64) * 512 + kk); \
    ra_lo0 = *(const uint4*)(gAlo + (size_t)a_r * 512 + kk); \
    ra_lo1 = *(const uint4*)(gAlo + (size_t)(a_r + 64) * 512 + kk); \
    rb_hi  = *(const uint4*)(gBhi + (size_t)a_r * 512 + kk); \
    rb_lo  = *(const uint4*)(gBlo + (size_t)a_r * 512 + kk); \
} while (0)

#define STORE_TILE(s) do { \
    int ao = a_r * 80 + a_q * 16; \
    *(uint4*)(smc + (s) * 10240 + ao) = ra_hi0; \
    *(uint4*)(smc + (s) * 10240 + ao + 64 * 80) = ra_hi1; \
    *(uint4*)(smc + 20480 + (s) * 10240 + ao) = ra_lo0; \
    *(uint4*)(smc + 20480 + (s) * 10240 + ao + 64 * 80) = ra_lo1; \
    if (a_r < 64) { \
        *(uint4*)(smc + 40960 + (s) * 5120 + ao) = rb_hi; \
        *(uint4*)(smc + 51200 + (s) * 5120 + ao) = rb_lo; \
    } \
} while (0)

    LOAD_TILE(0);
    STORE_TILE(0);
    __syncthreads();

    for (int kt = 0; kt < 16; kt++) {
        if (kt < 15) LOAD_TILE(kt + 1);
        int s = kt & 1;
        uint32_t as  = aAddr + s * 10240;
        uint32_t als = as + 20480;
        uint32_t bs  = bAddr + s * 5120;
        uint32_t bls = bs + 10240;
#pragma unroll
        for (int ks2 = 0; ks2 < 2; ks2++) {
            uint32_t ka = ks2 * 32;
            uint32_t ahi[2][4], alo[2][4], bhi[2][4], blo[2][4];
            ldsm4(ahi[0], as + ka);
            ldsm4(ahi[1], as + 1280 + ka);
            ldsm4(alo[0], als + ka);
            ldsm4(alo[1], als + 1280 + ka);
            ldsm4(bhi[0], bs + ka);
            ldsm4(bhi[1], bs + 1280 + ka);
            ldsm4(blo[0], bls + ka);
            ldsm4(blo[1], bls + 1280 + ka);
#pragma unroll
            for (int mt = 0; mt < 2; mt++) {
#pragma unroll
                for (int nt = 0; nt < 4; nt++) {
                    const uint32_t* bh = &bhi[nt >> 1][(nt & 1) * 2];
                    const uint32_t* bl = &blo[nt >> 1][(nt & 1) * 2];
                    mma_bf16(acc[mt][nt], ahi[mt], bh);
                    mma_bf16(acc[mt][nt], ahi[mt], bl);
                    mma_bf16(acc[mt][nt], alo[mt], bh);
                }
            }
        }
        if (kt < 15) STORE_TILE((kt + 1) & 1);
        __syncthreads();
    }
#undef LOAD_TILE
#undef STORE_TILE
}

// ---------------- proj HMMA ----------------
__global__ __launch_bounds__(256, 2) void proj_mma_kernel()
{
    int m0 = blockIdx.x * 128;
    int n0 = blockIdx.y * 64;
    int z = blockIdx.z;
    int proj = z >> 1, ie = z & 1;
    int tid = (proj <= 1) ? 0 : (proj <= 3) ? 1 : 2;

    const __nv_bfloat16* ahi = g_Ahi + ((size_t)(tid * 2 + ie) * 1024 + m0) * 512;
    const __nv_bfloat16* alo = g_Alo + ((size_t)(tid * 2 + ie) * 1024 + m0) * 512;
    const __nv_bfloat16* bhi = g_WThi + ((size_t)(proj * 2 + ie) * 512 + n0) * 512;
    const __nv_bfloat16* blo = g_WTlo + ((size_t)(proj * 2 + ie) * 512 + n0) * 512;

    float acc[2][4][4];
#pragma unroll
    for (int a = 0; a < 2; a++)
#pragma unroll
        for (int b = 0; b < 4; b++)
#pragma unroll
            for (int c = 0; c < 4; c++) acc[a][b][c] = 0.f;

    hmma_mainloop(ahi, alo, bhi, blo, acc);

    int t = threadIdx.x, lane = t & 31, warp = t >> 5;
    int wm = (warp & 3) * 32, wn = (warp >> 2) * 32;
    int r_in = lane >> 2, cc = (lane & 3) * 2;

    if (proj == 2 || proj == 3) {
        int set = proj - 2;
#pragma unroll
        for (int mt = 0; mt < 2; mt++) {
#pragma unroll
            for (int nt = 0; nt < 4; nt++) {
                int f0 = n0 + wn + nt * 8 + cc;
#pragma unroll
                for (int half = 0; half < 2; half++) {
                    int m = m0 + wm + mt * 16 + r_in + half * 8;
                    int bb = m >> 8, ll = m & 255;
#pragma unroll
                    for (int e = 0; e < 2; e++) {
                        int f = f0 + e;
                        int hh = f >> 6, dd = f & 63;
                        g_kpT[((size_t)((bb * 8 + hh) * 64 + dd)) * 1024 + (ll * 2 + ie) * 2 + set] =
                            acc[mt][nt][half * 2 + e];
                    }
                }
            }
        }
    } else {
        float* dst = (proj == 0) ? g_qp : (proj == 1) ? g_qp2 : g_vp;
#pragma unroll
        for (int mt = 0; mt < 2; mt++) {
#pragma unroll
            for (int nt = 0; nt < 4; nt++) {
                int f0 = n0 + wn + nt * 8 + cc;
#pragma unroll
                for (int half = 0; half < 2; half++) {
                    int m = m0 + wm + mt * 16 + r_in + half * 8;
                    float2 st = make_float2(acc[mt][nt][half * 2], acc[mt][nt][half * 2 + 1]);
                    *(float2*)(dst + ((size_t)m * 2 + ie) * 512 + f0) = st;
                }
            }
        }
    }
}

// ---------------- fc HMMA (+residual) ----------------
__global__ __launch_bounds__(256, 2) void fc_mma_kernel(const float* __restrict__ qin)
{
    int m0 = blockIdx.x * 128;
    int n0 = blockIdx.y * 64;
    int ie = blockIdx.z;

    const __nv_bfloat16* ahi = g_Phi + ((size_t)ie * 1024 + m0) * 512;
    const __nv_bfloat16* alo = g_Plo + ((size_t)ie * 1024 + m0) * 512;
    const __nv_bfloat16* bhi = g_WThi + ((size_t)(10 + ie) * 512 + n0) * 512;
    const __nv_bfloat16* blo = g_WTlo + ((size_t)(10 + ie) * 512 + n0) * 512;

    float acc[2][4][4];
#pragma unroll
    for (int a = 0; a < 2; a++)
#pragma unroll
        for (int b = 0; b < 4; b++)
#pragma unroll
            for (int c = 0; c < 4; c++) acc[a][b][c] = 0.f;

    hmma_mainloop(ahi, alo, bhi, blo, acc);

    int t = threadIdx.x, lane = t & 31, warp = t >> 5;
    int wm = (warp & 3) * 32, wn = (warp >> 2) * 32;
    int r_in = lane >> 2, cc = (lane & 3) * 2;

#pragma unroll
    for (int mt = 0; mt < 2; mt++) {
#pragma unroll
        for (int nt = 0; nt < 4; nt++) {
            int f0 = n0 + wn + nt * 8 + cc;
#pragma unroll
            for (int half = 0; half < 2; half++) {
                int m = m0 + wm + mt * 16 + r_in + half * 8;
                size_t off = ((size_t)m * 2 + ie) * 512 + f0;
                float2 rv = *(const float2*)(qin + off);
                float2 st = make_float2(acc[mt][nt][half * 2] + rv.x,
                                        acc[mt][nt][half * 2 + 1] + rv.y);
                *(float2*)(g_res + off) = st;
            }
        }
    }
}

// ======================================================================
// gate MLP via fp16 HMMA (single pass), 4 q per block
// ======================================================================
#define GOFF_XH   24576
#define GOFF_BW   73728
#define GOFF_B2   77824
#define GATE_SMEM 77952

__device__ __forceinline__ float lsgf(float a) {
    return fminf(a, 0.f) - __logf(1.f + __expf(-fabsf(a)));
}

__global__ __launch_bounds__(256, 2) void gate_mma_kernel(
    const float* __restrict__ grb1, const float* __restrict__ grW2,
    const float* __restrict__ grb2)
{
    extern __shared__ char gsm[];
    uint4* smW1 = (uint4*)gsm;
    uint4* smX  = (uint4*)(gsm + GOFF_XH);
    float2* bw = (float2*)(gsm + GOFF_BW);
    float* b2s = (float*)(gsm + GOFF_B2);

    int t = threadIdx.x, lane = t & 31, w = t >> 5;
    int blk = blockIdx.x, b = blk >> 6, q0 = (blk & 63) * 4;

    const uint4* srcW1 = (const uint4*)g_W1h;
    size_t xb = ((size_t)(b * 256 + q0)) * 6144;
    const uint4* srcX = (const uint4*)(g_Xh + xb);
#pragma unroll
    for (int i = 0; i < 6; i++) {
        int idx = t + i * 256;
        smW1[idx] = srcW1[idx];
    }
#pragma unroll
    for (int i = 0; i < 12; i++) {
        int idx = t + i * 256;
        smX[idx] = srcX[idx];
    }
    for (int idx = t; idx < 512; idx += 256) {
        int c = idx >> 4, jj = (idx >> 2) & 3, s = idx & 3;
        int m = (s >> 1) * 8 + 2 * jj + (s & 1);
        bw[idx] = make_float2(grb1[c * 16 + m], grW2[c * 16 + m]);
    }
    if (t < 32) b2s[t] = grb2[t];
    __syncthreads();

    uint32_t sb = smem_u32(gsm);
    int r0 = w * 32;

    uint32_t ah[4][2][4];
#pragma unroll
    for (int qq = 0; qq < 4; qq++) {
        uint32_t a0 = sb + GOFF_XH +
            (uint32_t)((qq * 256 + r0 + (lane & 15)) * 48 + (lane >> 4) * 16);
        ldsm4(ah[qq][0], a0);
        ldsm4(ah[qq][1], a0 + 16 * 48);
    }

    int j = lane & 3, rg = lane >> 2;
    uint32_t bAddrBase = sb +
        (uint32_t)((((lane & 7) + ((lane >> 4) & 1) * 8)) * 48 + ((lane >> 3) & 1) * 16);
    float* outb = g_lsg + ((size_t)(b * 256 + q0)) * 8192;

    for (int c = 0; c < 32; c++) {
        uint32_t bh[4];
        ldsm4(bh, bAddrBase + (uint32_t)(c * 768));

        float acc[4][2][2][4];
#pragma unroll
        for (int qq = 0; qq < 4; qq++)
#pragma unroll
            for (int rt = 0; rt < 2; rt++)
#pragma unroll
                for (int nt = 0; nt < 2; nt++)
#pragma unroll
                    for (int e = 0; e < 4; e++) acc[qq][rt][nt][e] = 0.f;

#pragma unroll
        for (int qq = 0; qq < 4; qq++)
#pragma unroll
            for (int rt = 0; rt < 2; rt++)
#pragma unroll
                for (int nt = 0; nt < 2; nt++)
                    mma_f16(acc[qq][rt][nt], ah[qq][rt], &bh[nt * 2]);

        float2 p[4];
        *(float4*)&p[0] = *(const float4*)&bw[(c * 4 + j) * 4];
        *(float4*)&p[2] = *(const float4*)&bw[(c * 4 + j) * 4 + 2];
        float b2 = b2s[c];

#pragma unroll
        for (int qq = 0; qq < 4; qq++) {
            float v[4];
#pragma unroll
            for (int rt = 0; rt < 2; rt++) {
                float s0 = 0.f, s1 = 0.f;
#pragma unroll
                for (int nt = 0; nt < 2; nt++) {
#pragma unroll
                    for (int e = 0; e < 2; e++) {
                        int s = nt * 2 + e;
                        s0 += fmaxf(acc[qq][rt][nt][e]     + p[s].x, 0.f) * p[s].y;
                        s1 += fmaxf(acc[qq][rt][nt][2 + e] + p[s].x, 0.f) * p[s].y;
                    }
                }
                v[rt * 2] = s0; v[rt * 2 + 1] = s1;
            }
#pragma unroll
            for (int o = 1; o <= 2; o <<= 1) {
#pragma unroll
                for (int i = 0; i < 4; i++) v[i] += __shfl_xor_sync(0xffffffffu, v[i], o);
            }
            if (j == 0) {
                float* ob = outb + (size_t)qq * 8192;
                int lbase = r0 + rg;
                ob[c * 256 + lbase]      = lsgf(v[0] + b2);
                ob[c * 256 + lbase + 8]  = lsgf(v[1] + b2);
                ob[c * 256 + lbase + 16] = lsgf(v[2] + b2);
                ob[c * 256 + lbase + 24] = lsgf(v[3] + b2);
            }
        }
    }
}

// ======================================================================
// fused attention — transposed smem layouts (occupancy 2) [R12 best]
// ======================================================================
#define AOFF_SS   9216
#define AOFF_EXP  41984
#define AOFF_SSUM 74752
#define ATTN_SMEM 74816

__global__ __launch_bounds__(256, 2) void attn_kernel(
    const float* __restrict__ adj, const int* __restrict__ mask)
{
    extern __shared__ char dsm[];
    float2* sqpT = (float2*)dsm;
    float2* ss2  = (float2*)(dsm + AOFF_SS);
    float2* expb = (float2*)(dsm + AOFF_EXP);
    float*  ssum = (float*)(dsm + AOFF_SSUM);

    int bx = blockIdx.x;
    int qt = bx & 15;
    int h  = (bx >> 4) & 7;
    int ie = (bx >> 7) & 1;
    int b  = bx >> 8;
    int q0 = qt * 16;

    int t = threadIdx.x;

#pragma unroll
    for (int i = 0; i < 4; i++) {
        int idx = t + i * 256;
        int qq = idx >> 6, d = idx & 63;
        size_t off = ((size_t)(b * 256 + q0 + qq) * 2 + ie) * 512 + h * 64 + d;
        sqpT[d * 18 + qq] = make_float2(g_qp[off], g_qp2[off]);
    }
    __syncthreads();

    // -------- score phase --------
    {
        ull acc0[16], acc1[16];
#pragma unroll
        for (int qq = 0; qq < 16; qq++) { acc0[qq] = 0ull; acc1[qq] = 0ull; }

        const float4* kptr = (const float4*)g_kpT + ((size_t)(b * 8 + h) * 64) * 256 + t;
#pragma unroll 8
        for (int d = 0; d < 64; d++) {
            float4 kv = kptr[(size_t)d * 256];
            ull kp0 = pk(kv.x, kv.y), kp1 = pk(kv.z, kv.w);
            const ulonglong2* qrow = (const ulonglong2*)(sqpT + (size_t)d * 18);
#pragma unroll
            for (int j = 0; j < 8; j++) {
                ulonglong2 qv = qrow[j];
                fma2(acc0[2 * j],     qv.x, kp0);
                fma2(acc1[2 * j],     qv.x, kp1);
                fma2(acc0[2 * j + 1], qv.y, kp0);
                fma2(acc1[2 * j + 1], qv.y, kp1);
            }
        }

        int c0 = (ie * 2 + 0) * 8 + h;
        int c1 = (ie * 2 + 1) * 8 + h;
#pragma unroll
        for (int qq = 0; qq < 16; qq++) {
            int qi = q0 + qq;
            int mrow = b * 65536 + qi * 256 + t;
            int mv = mask[mrow];
            float at = (t <= qi) ? adj[mrow] : 0.f;
            float s1a, s2a, s1b, s2b;
            unpk(s1a, s2a, acc0[qq]);
            unpk(s1b, s2b, acc1[qq]);
            float sa, sb;
            if (mv == 0) {
                sa = -1e9f; sb = -1e9f;
            } else {
                size_t lbase = ((size_t)(b * 256 + qi) * 32) * 256 + t;
                float l0 = g_lsg[lbase + (size_t)c0 * 256];
                float l1 = g_lsg[lbase + (size_t)c1 * 256];
                sa = (s1a * at + s2a * (1.f - at)) * 0.125f + l0;
                sb = (s1b * at + s2b * (1.f - at)) * 0.125f + l1;
            }
            ss2[qq * 256 + t] = make_float2(sa, sb);
        }
    }
    __syncthreads();

    // -------- softmax --------
    {
        int lane = t & 31, w = t >> 5;
        float2* r0 = ss2 + (2 * w) * 256;
        float2* r1 = r0 + 256;
        float2 v0[8], v1[8];
        float mx0 = -1e30f, mx1 = -1e30f;
#pragma unroll
        for (int i = 0; i < 8; i++) {
            v0[i] = r0[lane + 32 * i];
            v1[i] = r1[lane + 32 * i];
            mx0 = fmaxf(mx0, fmaxf(v0[i].x, v0[i].y));
            mx1 = fmaxf(mx1, fmaxf(v1[i].x, v1[i].y));
        }
#pragma unroll
        for (int o = 16; o > 0; o >>= 1) {
            mx0 = fmaxf(mx0, __shfl_xor_sync(0xffffffffu, mx0, o));
            mx1 = fmaxf(mx1, __shfl_xor_sync(0xffffffffu, mx1, o));
        }
        float s0 = 0.f, s1 = 0.f;
#pragma unroll
        for (int i = 0; i < 8; i++) {
            v0[i].x = __expf(v0[i].x - mx0); v0[i].y = __expf(v0[i].y - mx0);
            v1[i].x = __expf(v1[i].x - mx1); v1[i].y = __expf(v1[i].y - mx1);
            s0 += v0[i].x + v0[i].y;
            s1 += v1[i].x + v1[i].y;
        }
#pragma unroll
        for (int o = 16; o > 0; o >>= 1) {
            s0 += __shfl_xor_sync(0xffffffffu, s0, o);
            s1 += __shfl_xor_sync(0xffffffffu, s1, o);
        }
        if (lane == 0) { ssum[2 * w] = s0; ssum[2 * w + 1] = s1; }
        __syncwarp();
#pragma unroll
        for (int i = 0; i < 8; i++) {
            int c = lane + 32 * i;
            int pa = 2 * c, pb = 2 * c + 1;
            expb[pa * 8 + ((w + pa + (pa >> 3)) & 7)] = make_float2(v0[i].x, v1[i].x);
            expb[pb * 8 + ((w + pb + (pb >> 3)) & 7)] = make_float2(v0[i].y, v1[i].y);
        }
    }
    __syncthreads();

    // -------- PV phase --------
    {
        int d = t & 63, grp = t >> 6;
        const float* vb = g_vp + ((size_t)b * 512) * 512 + h * 64 + d;
        ull o[8];
#pragma unroll
        for (int r = 0; r < 8; r++) o[r] = 0ull;
        int p0 = grp * 128;
#pragma unroll 64
        for (int pp = 0; pp < 128; pp++) {
            int p = p0 + pp;
            const ulonglong2* row = (const ulonglong2*)(expb + (size_t)p * 8);
            ulonglong2 e0 = row[0], e1 = row[1], e2 = row[2], e3 = row[3];
            ull ev[8] = {e0.x, e0.y, e1.x, e1.y, e2.x, e2.y, e3.x, e3.y};
            float v = __ldg(vb + (size_t)p * 512);
            ull vd = pk(v, v);
            int rot = (pp + (pp >> 3)) & 7;
#pragma unroll
            for (int r = 0; r < 8; r++) fma2(o[r], ev[(r + rot) & 7], vd);
        }
        __syncthreads();
        float* spv = (float*)(dsm + AOFF_SS);
        if (grp) {
            float* sp = spv + (grp - 1) * 1024;
#pragma unroll
            for (int r = 0; r < 8; r++) {
                float lo, hi;
                unpk(lo, hi, o[r]);
                sp[(2 * r) * 64 + d] = lo;
                sp[(2 * r + 1) * 64 + d] = hi;
            }
        }
        __syncthreads();
        if (grp == 0) {
#pragma unroll
            for (int r = 0; r < 8; r++) {
                float lo, hi;
                unpk(lo, hi, o[r]);
                float sum0 = lo + spv[(2 * r) * 64 + d] + spv[1024 + (2 * r) * 64 + d] + spv[2048 + (2 * r) * 64 + d];
                float sum1 = hi + spv[(2 * r + 1) * 64 + d] + spv[1024 + (2 * r + 1) * 64 + d] + spv[2048 + (2 * r + 1) * 64 + d];
                int qq0 = 2 * r, qq1 = 2 * r + 1;
                float o0 = sum0 / ssum[qq0];
                float o1 = sum1 / ssum[qq1];
                __nv_bfloat16 ph0, pl0, ph1, pl1;
                bsplit(o0, ph0, pl0);
                bsplit(o1, ph1, pl1);
                size_t row0 = (size_t)ie * 1024 + (b * 256 + q0 + qq0);
                size_t off0 = row0 * 512 + h * 64 + d;
                size_t off1 = off0 + 512;
                g_Phi[off0] = ph0; g_Plo[off0] = pl0;
                g_Phi[off1] = ph1; g_Plo[off1] = pl1;
            }
        }
    }
}

// ---------------- layernorm: 2 rows per block ----------------
__global__ __launch_bounds__(256) void ln_kernel(
    const float* __restrict__ ln_g, const float* __restrict__ ln_b,
    float* __restrict__ out)
{
    __shared__ float rs[8], rq[8];
    __shared__ float s_mu[2], s_inv[2];
    int grp = threadIdx.x >> 7;           // 0 or 1
    int row = blockIdx.x * 2 + grp;
    int t = threadIdx.x & 127;
    const float4 v = ((const float4*)(g_res + (size_t)row * 512))[t];
    float sum = v.x + v.y + v.z + v.w;
    float sq  = v.x * v.x + v.y * v.y + v.z * v.z + v.w * v.w;
#pragma unroll
    for (int o = 16; o > 0; o >>= 1) {
        sum += __shfl_xor_sync(0xffffffffu, sum, o);
        sq  += __shfl_xor_sync(0xffffffffu, sq, o);
    }
    int lane = t & 31, warp = threadIdx.x >> 5;   // 0..7
    if (lane == 0) { rs[warp] = sum; rq[warp] = sq; }
    __syncthreads();
    if (t == 0) {
        int w0 = grp * 4;
        float S = rs[w0] + rs[w0 + 1] + rs[w0 + 2] + rs[w0 + 3];
        float Q = rq[w0] + rq[w0 + 1] + rq[w0 + 2] + rq[w0 + 3];
        float mu = S * (1.f / 512.f);
        float var = Q * (1.f / 512.f) - mu * mu;
        s_mu[grp] = mu;
        s_inv[grp] = rsqrtf(var + 1e-6f);
    }
    __syncthreads();
    float mu = s_mu[grp], inv = s_inv[grp];
    float4 g4 = ((const float4*)ln_g)[t];
    float4 b4 = ((const float4*)ln_b)[t];
    float4 y;
    y.x = (v.x - mu) * inv * g4.x + b4.x;
    y.y = (v.y - mu) * inv * g4.y + b4.y;
    y.z = (v.z - mu) * inv * g4.z + b4.z;
    y.w = (v.w - mu) * inv * g4.w + b4.w;
    ((float4*)(out + (size_t)row * 512))[t] = y;
}

extern "C" void kernel_launch(void* const* d_in, const int* in_sizes, int n_in,
                              void* d_out, int out_size) {
    const float* q       = (const float*)d_in[0];
    const float* k       = (const float*)d_in[1];
    const float* v       = (const float*)d_in[2];
    const int*   mask    = (const int*)d_in[3];
    const float* gr_mask = (const float*)d_in[4];
    const float* adj     = (const float*)d_in[5];
    const float* Wq      = (const float*)d_in[6];
    const float* Wk      = (const float*)d_in[7];
    const float* Wv      = (const float*)d_in[8];
    const float* Wq2     = (const float*)d_in[9];
    const float* Wk2     = (const float*)d_in[10];
    const float* Wfc     = (const float*)d_in[12];
    const float* grW1    = (const float*)d_in[13];
    const float* grb1    = (const float*)d_in[14];
    const float* grW2    = (const float*)d_in[15];
    const float* grb2    = (const float*)d_in[16];
    const float* ln_g    = (const float*)d_in[17];
    const float* ln_b    = (const float*)d_in[18];
    float* out = (float*)d_out;

    cudaFuncSetAttribute(proj_mma_kernel, cudaFuncAttributeMaxDynamicSharedMemorySize, GEMM_SMEM);
    cudaFuncSetAttribute(fc_mma_kernel, cudaFuncAttributeMaxDynamicSharedMemorySize, GEMM_SMEM);
    cudaFuncSetAttribute(gate_mma_kernel, cudaFuncAttributeMaxDynamicSharedMemorySize, GATE_SMEM);
    cudaFuncSetAttribute(attn_kernel, cudaFuncAttributeMaxDynamicSharedMemorySize, ATTN_SMEM);

    static cudaStream_t s1 = nullptr, s2 = nullptr, s3 = nullptr;
    static cudaEvent_t e0 = nullptr, e1 = nullptr, e2 = nullptr, e3 = nullptr;
    if (s1 == nullptr) {
        cudaStreamCreateWithFlags(&s1, cudaStreamNonBlocking);
        cudaStreamCreateWithFlags(&s2, cudaStreamNonBlocking);
        cudaStreamCreateWithFlags(&s3, cudaStreamNonBlocking);
        cudaEventCreateWithFlags(&e0, cudaEventDisableTiming);
        cudaEventCreateWithFlags(&e1, cudaEventDisableTiming);
        cudaEventCreateWithFlags(&e2, cudaEventDisableTiming);
        cudaEventCreateWithFlags(&e3, cudaEventDisableTiming);
    }

    cudaEventRecord(e0, 0);
    cudaStreamWaitEvent(s1, e0, 0);
    cudaStreamWaitEvent(s2, e0, 0);
    cudaStreamWaitEvent(s3, e0, 0);

    // chain A: weights on s1, activations on s3, proj joins both on s1
    conv_w_kernel<<<dim3(16, 16, 12), 256, 0, s1>>>(Wq, Wq2, Wk, Wk2, Wv, Wfc);
    conv_a_kernel<<<3072, 256, 0, s3>>>(q, k, v);
    cudaEventRecord(e3, s3);
    cudaStreamWaitEvent(s1, e3, 0);
    proj_mma_kernel<<<dim3(8, 8, 10), 256, GEMM_SMEM, s1>>>();
    cudaEventRecord(e1, s1);

    // chain B: gate (fp16 single-pass)
    conv_x_kernel<<<1025, 256, 0, s2>>>(gr_mask, grW1);
    gate_mma_kernel<<<256, 256, GATE_SMEM, s2>>>(grb1, grW2, grb2);
    cudaEventRecord(e2, s2);

    // join
    cudaStreamWaitEvent(0, e1, 0);
    cudaStreamWaitEvent(0, e2, 0);

    attn_kernel<<<1024, 256, ATTN_SMEM>>>(adj, mask);
    fc_mma_kernel<<<dim3(8, 8, 2), 256, GEMM_SMEM>>>(q);
    ln_kernel<<<1024, 256>>>(ln_g, ln_b, out);
}